// round 14
// baseline (speedup 1.0000x reference)
#include <cuda_runtime.h>
#include <math.h>

#define TT   500
#define BB   256
#define ENCN 700
#define HIDN 128
#define LCAP 128          // list capacity (u32 entries) per (b,t); mean firing 35
#define NTHD 32768        // BB*HIDN
#define CHB  64           // batch-chunk size (4 chunks pipelined)
#define NBATCH 50         // TT/10 scan batches
#define ZSENT (ENCN << 8) // sentinel byte-offset -> zero smem row (row stride 256 B)

// ---------------- static device scratch (allocation-free rule) ----------------
__device__ float          g_w1t[ENCN * HIDN];               // w1 transposed [enc][hid]
__device__ int            g_cnt [BB * TT];                  // firing count per (b,t)
__device__ unsigned int   g_list[(size_t)BB * TT * LCAP];   // byte offsets e<<8, 8-padded
__device__ float          g_h   [(size_t)TT * BB * HIDN];   // layer-1 pre-filter activations
__device__ unsigned char  g_s1b [(size_t)TT * BB * HIDN];   // layer-1 spikes as bytes
__device__ float          g_o   [TT * BB];                  // layer-2 pre-filter input

// Constants exactly as XLA-on-GPU computes them (bit-exact — DO NOT TOUCH):
__device__ __forceinline__ void snn_consts(float& d, float& cd1, float& cdr) {
    d        = expf(-0.05f);          // libdevice __nv_expf
    float e1 = expf(1.0f);
    float c1 = __fdiv_rn(e1, 20.0f);
    cd1      = __fmul_rn(c1, d);
    float cr = __fdiv_rn(__fmul_rn(-2.0f, e1), 20.0f);
    cdr      = __fmul_rn(cr, d);
}

// ptxas-contracted scan step (bit-exact — DO NOT TOUCH):
__device__ __forceinline__ void alpha_step(float d, float cd, float& p, float& q, float in) {
    q = fmaf(d, q, __fmul_rn(cd, p));
    p = fmaf(d, p, in);
}

// ---------------- K_t: transpose w1 [hid][enc] -> [enc][hid] ----------------
__global__ void k_transpose(const float* __restrict__ w1) {
    int i = blockIdx.x * blockDim.x + threadIdx.x;
    if (i < ENCN * HIDN) {
        int e = i >> 7;
        int h = i & (HIDN - 1);
        g_w1t[i] = w1[h * ENCN + e];
    }
}

// ---------------- K0: ballot-compact u32 byte-offsets per (b,t), 8-padded ----------------
__global__ __launch_bounds__(256) void k_compact(const float* __restrict__ x, int b0) {
    int b    = b0 + blockIdx.y;
    int t    = blockIdx.x * 8 + (threadIdx.x >> 5);
    int lane = threadIdx.x & 31;
    if (t >= TT) return;

    const float4* xr4 = (const float4*)(x + (size_t)b * (TT * ENCN) + (size_t)t * ENCN);

    float4 v[6];
#pragma unroll
    for (int g = 0; g < 6; ++g) {
        int idx = g * 32 + lane;                 // float4 index, 175 per row
        v[g] = (idx < 175) ? __ldg(xr4 + idx)
                           : make_float4(0.f, 0.f, 0.f, 0.f);
    }

    unsigned int* lst = g_list + ((size_t)b * TT + t) * LCAP;
    const unsigned lt = (1u << lane) - 1u;
    int cnt = 0;
#pragma unroll
    for (int g = 0; g < 6; ++g) {
        bool f0 = v[g].x > 0.5f, f1 = v[g].y > 0.5f, f2 = v[g].z > 0.5f, f3 = v[g].w > 0.5f;
        unsigned m0 = __ballot_sync(0xffffffffu, f0);
        unsigned m1 = __ballot_sync(0xffffffffu, f1);
        unsigned m2 = __ballot_sync(0xffffffffu, f2);
        unsigned m3 = __ballot_sync(0xffffffffu, f3);
        int p = cnt + __popc(m0 & lt) + __popc(m1 & lt) + __popc(m2 & lt) + __popc(m3 & lt);
        unsigned e0s = (unsigned)((g * 128 + lane * 4) << 8);   // byte offsets, row stride 256
        if (f0) { if (p < LCAP) lst[p] = e0s;         ++p; }
        if (f1) { if (p < LCAP) lst[p] = e0s + 256;   ++p; }
        if (f2) { if (p < LCAP) lst[p] = e0s + 512;   ++p; }
        if (f3) { if (p < LCAP) lst[p] = e0s + 768;   ++p; }
        cnt += __popc(m0) + __popc(m1) + __popc(m2) + __popc(m3);
    }
    cnt = cnt < LCAP ? cnt : LCAP;
    // sentinel-pad [cnt, ceil8(cnt)) (<=7 entries) so gather groups are branch-free
    int padEnd = (cnt + 7) & ~7;
    if (padEnd > 48) padEnd = 48;                // entries beyond 48 handled by tail loop
    for (int i = cnt + lane; i < padEnd; i += 32) lst[i] = (unsigned)ZSENT;
    if (lane == 0) g_cnt[b * TT + t] = cnt;
}

// ---------------- K_A: sparse gather GEMM, 64-wide LDS.64, DUAL-t per warp ----------------
// grid (CHB, 2), 512 thr, 1 block/SM. Each warp processes two independent t's per
// iteration (tA in [0,250), tB = tA+250): 4 independent accumulator chains, both
// list prefetches issued up front -> per-t latency exposure halves vs R13.
// Per element per t: IADD + LDS.64 + 2 FADD. Sentinel row 700 = zeros (+0.0f exact);
// per-column ascending-e serial order preserved (bit-exact).
__global__ __launch_bounds__(512, 1) void k_gather(int b0) {
    extern __shared__ float w1s[];   // [701][64] = 179456 B (row 700 = zeros)
    const int b = b0 + blockIdx.x, hh = blockIdx.y;
    const int tid  = threadIdx.x;
    const int wid  = tid >> 5;
    const int lane = tid & 31;

    for (int i = tid; i < (ENCN + 1) * 64; i += 512) {
        int e = i >> 6, h = i & 63;
        w1s[i] = (e < ENCN) ? g_w1t[e * HIDN + hh * 64 + h] : 0.0f;
    }
    __syncthreads();

    const char* wbase = (const char*)w1s + lane * 8;   // per-thread column pair base

    for (int tA = wid; tA < 250; tA += 16) {
        const int tB = tA + 250;
        const int baseA = b * TT + tA;
        const int baseB = b * TT + tB;
        const int nA = __ldg(g_cnt + baseA);
        const int nB = __ldg(g_cnt + baseB);
        const uint4* lA = (const uint4*)(g_list + (size_t)baseA * LCAP);
        const uint4* lB = (const uint4*)(g_list + (size_t)baseB * LCAP);

        // both lists prefetched up front (24 x LDG.128, broadcast within warp)
        uint4 vA[12], vB[12];
#pragma unroll
        for (int r = 0; r < 12; ++r) { vA[r] = __ldg(lA + r); vB[r] = __ldg(lB + r); }

        const int ngA = ((nA < 48 ? nA : 48) + 7) >> 3;   // groups of 8
        const int ngB = ((nB < 48 ? nB : 48) + 7) >> 3;
        float a0 = 0.0f, a1 = 0.0f, c0 = 0.0f, c1 = 0.0f;
#pragma unroll
        for (int g = 0; g < 6; ++g) {
            if (g < ngA) {
                unsigned o[8] = { vA[2*g].x,   vA[2*g].y,   vA[2*g].z,   vA[2*g].w,
                                  vA[2*g+1].x, vA[2*g+1].y, vA[2*g+1].z, vA[2*g+1].w };
#pragma unroll
                for (int k = 0; k < 8; ++k) {
                    float2 w = *(const float2*)(wbase + o[k]);
                    a0 = __fadd_rn(a0, w.x);
                    a1 = __fadd_rn(a1, w.y);
                }
            }
            if (g < ngB) {
                unsigned o[8] = { vB[2*g].x,   vB[2*g].y,   vB[2*g].z,   vB[2*g].w,
                                  vB[2*g+1].x, vB[2*g+1].y, vB[2*g+1].z, vB[2*g+1].w };
#pragma unroll
                for (int k = 0; k < 8; ++k) {
                    float2 w = *(const float2*)(wbase + o[k]);
                    c0 = __fadd_rn(c0, w.x);
                    c1 = __fadd_rn(c1, w.y);
                }
            }
        }
        // rare tails (P ~ 1.5% each): entries 48..n-1, still ascending
        if (nA > 48) {
            const unsigned int* lst = g_list + (size_t)baseA * LCAP;
            for (int k = 48; k < nA; ++k) {
                float2 w = *(const float2*)(wbase + __ldg(lst + k));
                a0 = __fadd_rn(a0, w.x);
                a1 = __fadd_rn(a1, w.y);
            }
        }
        if (nB > 48) {
            const unsigned int* lst = g_list + (size_t)baseB * LCAP;
            for (int k = 48; k < nB; ++k) {
                float2 w = *(const float2*)(wbase + __ldg(lst + k));
                c0 = __fadd_rn(c0, w.x);
                c1 = __fadd_rn(c1, w.y);
            }
        }

        const size_t ocol = (size_t)b * HIDN + hh * 64 + lane * 2;
        *(float2*)(g_h + (size_t)tA * NTHD + ocol) = make_float2(a0, a1);
        *(float2*)(g_h + (size_t)tB * NTHD + ocol) = make_float2(c0, c1);
    }
}

// ---------------- K_B: layer-1 scan, FULL batch, 4-deep rotating prefetch ----------------
__global__ __launch_bounds__(256, 1) void k_scan1() {
    int gid = blockIdx.x * 256 + threadIdx.x;   // b*128 + h

    float d, cd1, cdr;
    snn_consts(d, cd1, cdr);

    float p1 = 0.f, q1 = 0.f, pr = 0.f, qr = 0.f;
    float buf[4][10];

#pragma unroll
    for (int k = 0; k < 4; ++k)
#pragma unroll
        for (int j = 0; j < 10; ++j)
            buf[k][j] = __ldg(&g_h[(size_t)(k * 10 + j) * NTHD + gid]);

    for (int bi4 = 0; bi4 < NBATCH; bi4 += 4) {
#pragma unroll
        for (int s = 0; s < 4; ++s) {
            int bi = bi4 + s;
            if (bi < NBATCH) {
                int t0 = bi * 10;
#pragma unroll
                for (int j = 0; j < 10; ++j) {
                    alpha_step(d, cd1, p1, q1, buf[s][j]);
                    qr = fmaf(d, qr, __fmul_rn(cdr, pr));
                    float u = __fadd_rn(q1, qr);
                    float sv = (u >= 1.0f) ? 1.0f : 0.0f;
                    pr = fmaf(d, pr, sv);
                    g_s1b[(size_t)(t0 + j) * NTHD + gid] = (unsigned char)(u >= 1.0f);
                }
                int nb = bi + 4;
                if (nb < NBATCH) {
#pragma unroll
                    for (int j = 0; j < 10; ++j)
                        buf[s][j] = __ldg(&g_h[(size_t)(nb * 10 + j) * NTHD + gid]);
                }
            }
        }
    }
}

// ---------------- K_C: o[t,b] = serial ascending-h FFMA over byte spikes ----------------
__global__ __launch_bounds__(256) void k_dot2(const float* __restrict__ w2) {
    __shared__ float w2s[HIDN];
    if (threadIdx.x < HIDN) w2s[threadIdx.x] = w2[threadIdx.x];
    __syncthreads();

    int t = blockIdx.x;
    int b = threadIdx.x;
    const uint4* sp = (const uint4*)(g_s1b + (size_t)t * NTHD + b * HIDN);

    float acc = 0.0f;
#pragma unroll
    for (int j = 0; j < 8; ++j) {
        uint4 v = __ldg(sp + j);
        unsigned wrd[4] = { v.x, v.y, v.z, v.w };
#pragma unroll
        for (int k = 0; k < 4; ++k) {
            unsigned w = wrd[k];
            int base = j * 16 + k * 4;
            acc = fmaf((float)(w & 0xffu),         w2s[base + 0], acc);
            acc = fmaf((float)((w >> 8) & 0xffu),  w2s[base + 1], acc);
            acc = fmaf((float)((w >> 16) & 0xffu), w2s[base + 2], acc);
            acc = fmaf((float)(w >> 24),           w2s[base + 3], acc);
        }
    }
    g_o[t * BB + b] = acc;
}

// ---------------- K_D: layer-2 scan, FULL batch, 4-deep rotating prefetch ----------------
__global__ __launch_bounds__(BB, 1) void k_scan2(float* __restrict__ out) {
    int b = threadIdx.x;

    float d, cd1, cdr;
    snn_consts(d, cd1, cdr);

    float p2 = 0.f, q2 = 0.f, pr2 = 0.f, qr2 = 0.f;
    float buf[4][10];

#pragma unroll
    for (int k = 0; k < 4; ++k)
#pragma unroll
        for (int j = 0; j < 10; ++j)
            buf[k][j] = __ldg(&g_o[(k * 10 + j) * BB + b]);

    for (int bi4 = 0; bi4 < NBATCH; bi4 += 4) {
#pragma unroll
        for (int s = 0; s < 4; ++s) {
            int bi = bi4 + s;
            if (bi < NBATCH) {
                int t0 = bi * 10;
#pragma unroll
                for (int j = 0; j < 10; ++j) {
                    alpha_step(d, cd1, p2, q2, buf[s][j]);
                    qr2 = fmaf(d, qr2, __fmul_rn(cdr, pr2));
                    float u = __fadd_rn(q2, qr2);
                    float sv = (u >= 1.0f) ? 1.0f : 0.0f;
                    pr2 = fmaf(d, pr2, sv);
                    out[b * TT + (t0 + j)] = sv;
                }
                int nb = bi + 4;
                if (nb < NBATCH) {
#pragma unroll
                    for (int j = 0; j < 10; ++j)
                        buf[s][j] = __ldg(&g_o[(nb * 10 + j) * BB + b]);
                }
            }
        }
    }
}

// ---------------- launch: 3 streams; enqueue order keeps G0 at launch #4 for ncu ----------------
extern "C" void kernel_launch(void* const* d_in, const int* in_sizes, int n_in,
                              void* d_out, int out_size) {
    const float* x = nullptr, *w1 = nullptr, *w2 = nullptr;
    for (int i = 0; i < n_in; ++i) {
        if      (in_sizes[i] == BB * TT * ENCN) x  = (const float*)d_in[i];
        else if (in_sizes[i] == HIDN * ENCN)    w1 = (const float*)d_in[i];
        else if (in_sizes[i] == HIDN)           w2 = (const float*)d_in[i];
    }

    static cudaStream_t sC = 0, sG = 0, sS = 0;
    static cudaEvent_t  evFork, evC[4], evG[4], evS;
    static int inited = 0;
    if (!inited) {
        cudaFuncSetAttribute(k_gather, cudaFuncAttributeMaxDynamicSharedMemorySize,
                             (ENCN + 1) * 64 * (int)sizeof(float));
        cudaStreamCreateWithFlags(&sC, cudaStreamNonBlocking);
        cudaStreamCreateWithFlags(&sG, cudaStreamNonBlocking);
        cudaStreamCreateWithFlags(&sS, cudaStreamNonBlocking);
        cudaEventCreateWithFlags(&evFork, cudaEventDisableTiming);
        cudaEventCreateWithFlags(&evS,    cudaEventDisableTiming);
        for (int i = 0; i < 4; ++i) {
            cudaEventCreateWithFlags(&evC[i], cudaEventDisableTiming);
            cudaEventCreateWithFlags(&evG[i], cudaEventDisableTiming);
        }
        inited = 1;
    }

    cudaEventRecord(evFork, 0);
    cudaStreamWaitEvent(sC, evFork, 0);
    cudaStreamWaitEvent(sG, evFork, 0);

    const int GSM = (ENCN + 1) * 64 * (int)sizeof(float);

    // launch #1..#4: T, C0, C1, G0  -> ncu captures G0
    k_transpose<<<(ENCN * HIDN + 255) / 256, 256, 0, sG>>>(w1);
    k_compact<<<dim3((TT + 7) / 8, CHB), 256, 0, sC>>>(x, 0 * CHB);
    cudaEventRecord(evC[0], sC);
    k_compact<<<dim3((TT + 7) / 8, CHB), 256, 0, sC>>>(x, 1 * CHB);
    cudaEventRecord(evC[1], sC);
    cudaStreamWaitEvent(sG, evC[0], 0);
    k_gather<<<dim3(CHB, 2), 512, GSM, sG>>>(0 * CHB);
    cudaEventRecord(evG[0], sG);

    k_compact<<<dim3((TT + 7) / 8, CHB), 256, 0, sC>>>(x, 2 * CHB);
    cudaEventRecord(evC[2], sC);
    cudaStreamWaitEvent(sG, evC[1], 0);
    k_gather<<<dim3(CHB, 2), 512, GSM, sG>>>(1 * CHB);
    cudaEventRecord(evG[1], sG);

    k_compact<<<dim3((TT + 7) / 8, CHB), 256, 0, sC>>>(x, 3 * CHB);
    cudaEventRecord(evC[3], sC);
    cudaStreamWaitEvent(sG, evC[2], 0);
    k_gather<<<dim3(CHB, 2), 512, GSM, sG>>>(2 * CHB);
    cudaEventRecord(evG[2], sG);

    cudaStreamWaitEvent(sG, evC[3], 0);
    k_gather<<<dim3(CHB, 2), 512, GSM, sG>>>(3 * CHB);
    cudaEventRecord(evG[3], sG);

    cudaStreamWaitEvent(sS, evG[3], 0);
    k_scan1<<<NTHD / 256, 256, 0, sS>>>();
    k_dot2<<<TT, BB, 0, sS>>>(w2);
    k_scan2<<<1, BB, 0, sS>>>((float*)d_out);
    cudaEventRecord(evS, sS);
    cudaStreamWaitEvent(0, evS, 0);
}

// round 15
// speedup vs baseline: 1.0664x; 1.0664x over previous
#include <cuda_runtime.h>
#include <math.h>

#define TT   500
#define BB   256
#define ENCN 700
#define HIDN 128
#define LCAP 128          // list capacity (u32 entries) per (b,t); mean firing 35
#define NTHD 32768        // BB*HIDN
#define CHB  64           // batch-chunk size (4 chunks pipelined)
#define NBATCH 50         // TT/10 scan batches
#define ZSENT (ENCN << 8) // sentinel byte-offset -> zero smem row (row stride 256 B)
#define GTHR 768          // gather block threads (24 warps/SM, 1 block/SM)

// ---------------- static device scratch (allocation-free rule) ----------------
__device__ float          g_w1t[ENCN * HIDN];               // w1 transposed [enc][hid]
__device__ int            g_cnt [BB * TT];                  // firing count per (b,t)
__device__ unsigned int   g_list[(size_t)BB * TT * LCAP];   // byte offsets e<<8, 8-padded
__device__ float          g_h   [(size_t)TT * BB * HIDN];   // layer-1 pre-filter activations
__device__ unsigned char  g_s1b [(size_t)TT * BB * HIDN];   // layer-1 spikes as bytes
__device__ float          g_o   [TT * BB];                  // layer-2 pre-filter input

// Constants exactly as XLA-on-GPU computes them (bit-exact — DO NOT TOUCH):
__device__ __forceinline__ void snn_consts(float& d, float& cd1, float& cdr) {
    d        = expf(-0.05f);          // libdevice __nv_expf
    float e1 = expf(1.0f);
    float c1 = __fdiv_rn(e1, 20.0f);
    cd1      = __fmul_rn(c1, d);
    float cr = __fdiv_rn(__fmul_rn(-2.0f, e1), 20.0f);
    cdr      = __fmul_rn(cr, d);
}

// ptxas-contracted scan step (bit-exact — DO NOT TOUCH):
__device__ __forceinline__ void alpha_step(float d, float cd, float& p, float& q, float in) {
    q = fmaf(d, q, __fmul_rn(cd, p));
    p = fmaf(d, p, in);
}

// ---------------- K_t: transpose w1 [hid][enc] -> [enc][hid] ----------------
__global__ void k_transpose(const float* __restrict__ w1) {
    int i = blockIdx.x * blockDim.x + threadIdx.x;
    if (i < ENCN * HIDN) {
        int e = i >> 7;
        int h = i & (HIDN - 1);
        g_w1t[i] = w1[h * ENCN + e];
    }
}

// ---------------- K0: ballot-compact u32 byte-offsets per (b,t), 8-padded ----------------
__global__ __launch_bounds__(256) void k_compact(const float* __restrict__ x, int b0) {
    int b    = b0 + blockIdx.y;
    int t    = blockIdx.x * 8 + (threadIdx.x >> 5);
    int lane = threadIdx.x & 31;
    if (t >= TT) return;

    const float4* xr4 = (const float4*)(x + (size_t)b * (TT * ENCN) + (size_t)t * ENCN);

    float4 v[6];
#pragma unroll
    for (int g = 0; g < 6; ++g) {
        int idx = g * 32 + lane;                 // float4 index, 175 per row
        v[g] = (idx < 175) ? __ldg(xr4 + idx)
                           : make_float4(0.f, 0.f, 0.f, 0.f);
    }

    unsigned int* lst = g_list + ((size_t)b * TT + t) * LCAP;
    const unsigned lt = (1u << lane) - 1u;
    int cnt = 0;
#pragma unroll
    for (int g = 0; g < 6; ++g) {
        bool f0 = v[g].x > 0.5f, f1 = v[g].y > 0.5f, f2 = v[g].z > 0.5f, f3 = v[g].w > 0.5f;
        unsigned m0 = __ballot_sync(0xffffffffu, f0);
        unsigned m1 = __ballot_sync(0xffffffffu, f1);
        unsigned m2 = __ballot_sync(0xffffffffu, f2);
        unsigned m3 = __ballot_sync(0xffffffffu, f3);
        int p = cnt + __popc(m0 & lt) + __popc(m1 & lt) + __popc(m2 & lt) + __popc(m3 & lt);
        unsigned e0s = (unsigned)((g * 128 + lane * 4) << 8);   // byte offsets, row stride 256
        if (f0) { if (p < LCAP) lst[p] = e0s;         ++p; }
        if (f1) { if (p < LCAP) lst[p] = e0s + 256;   ++p; }
        if (f2) { if (p < LCAP) lst[p] = e0s + 512;   ++p; }
        if (f3) { if (p < LCAP) lst[p] = e0s + 768;   ++p; }
        cnt += __popc(m0) + __popc(m1) + __popc(m2) + __popc(m3);
    }
    cnt = cnt < LCAP ? cnt : LCAP;
    // sentinel-pad [cnt, ceil8(cnt)) (<=7 entries) so gather groups are branch-free
    int padEnd = (cnt + 7) & ~7;
    if (padEnd > 48) padEnd = 48;                // entries beyond 48 handled by tail loop
    for (int i = cnt + lane; i < padEnd; i += 32) lst[i] = (unsigned)ZSENT;
    if (lane == 0) g_cnt[b * TT + t] = cnt;
}

// ---------------- K_A: sparse gather GEMM, 64-wide LDS.64, 24 warps/SM ----------------
// grid (CHB, 2), 768 thr, 1 block/SM (179.5 KB smem). Warp-per-t stride 24; each lane
// covers 2 hid columns via one LDS.64 per firing enc. More resident warps (24 vs 16)
// drive smem-crossbar utilization up (the measured binding resource).
// Sentinel row 700 = zeros (+0.0f exact); ascending-e serial order per column.
__global__ __launch_bounds__(GTHR, 1) void k_gather(int b0) {
    extern __shared__ float w1s[];   // [701][64] = 179456 B (row 700 = zeros)
    const int b = b0 + blockIdx.x, hh = blockIdx.y;
    const int tid  = threadIdx.x;
    const int wid  = tid >> 5;       // 0..23
    const int lane = tid & 31;

    for (int i = tid; i < (ENCN + 1) * 64; i += GTHR) {
        int e = i >> 6, h = i & 63;
        w1s[i] = (e < ENCN) ? g_w1t[e * HIDN + hh * 64 + h] : 0.0f;
    }
    __syncthreads();

    const char* wbase = (const char*)w1s + lane * 8;   // per-thread column pair base

    for (int t = wid; t < TT; t += 24) {
        const int base = b * TT + t;
        const int n = __ldg(g_cnt + base);
        const uint4* l4 = (const uint4*)(g_list + (size_t)base * LCAP);

        // unconditional 12 x LDG.128 prefetch (48 entries; MLP=12)
        uint4 v[12];
#pragma unroll
        for (int r = 0; r < 12; ++r) v[r] = __ldg(l4 + r);

        const int ng = ((n < 48 ? n : 48) + 7) >> 3;   // groups of 8 (= 2 uint4)
        float a0 = 0.0f, a1 = 0.0f;
#pragma unroll
        for (int g = 0; g < 6; ++g) {
            if (g < ng) {
                unsigned o[8] = { v[2*g].x,   v[2*g].y,   v[2*g].z,   v[2*g].w,
                                  v[2*g+1].x, v[2*g+1].y, v[2*g+1].z, v[2*g+1].w };
#pragma unroll
                for (int k = 0; k < 8; ++k) {
                    float2 w = *(const float2*)(wbase + o[k]);
                    a0 = __fadd_rn(a0, w.x);
                    a1 = __fadd_rn(a1, w.y);
                }
            }
        }
        // rare tail (P ~ 1.5%): entries 48..n-1, still ascending
        if (n > 48) {
            const unsigned int* lst = g_list + (size_t)base * LCAP;
            for (int k = 48; k < n; ++k) {
                float2 w = *(const float2*)(wbase + __ldg(lst + k));
                a0 = __fadd_rn(a0, w.x);
                a1 = __fadd_rn(a1, w.y);
            }
        }

        float2* outp = (float2*)(g_h + (size_t)t * NTHD + b * HIDN + hh * 64 + lane * 2);
        *outp = make_float2(a0, a1);
    }
}

// ---------------- K_B: layer-1 scan, FULL batch, 4-deep rotating prefetch ----------------
__global__ __launch_bounds__(256, 1) void k_scan1() {
    int gid = blockIdx.x * 256 + threadIdx.x;   // b*128 + h

    float d, cd1, cdr;
    snn_consts(d, cd1, cdr);

    float p1 = 0.f, q1 = 0.f, pr = 0.f, qr = 0.f;
    float buf[4][10];

#pragma unroll
    for (int k = 0; k < 4; ++k)
#pragma unroll
        for (int j = 0; j < 10; ++j)
            buf[k][j] = __ldg(&g_h[(size_t)(k * 10 + j) * NTHD + gid]);

    for (int bi4 = 0; bi4 < NBATCH; bi4 += 4) {
#pragma unroll
        for (int s = 0; s < 4; ++s) {
            int bi = bi4 + s;
            if (bi < NBATCH) {
                int t0 = bi * 10;
#pragma unroll
                for (int j = 0; j < 10; ++j) {
                    alpha_step(d, cd1, p1, q1, buf[s][j]);
                    qr = fmaf(d, qr, __fmul_rn(cdr, pr));
                    float u = __fadd_rn(q1, qr);
                    float sv = (u >= 1.0f) ? 1.0f : 0.0f;
                    pr = fmaf(d, pr, sv);
                    g_s1b[(size_t)(t0 + j) * NTHD + gid] = (unsigned char)(u >= 1.0f);
                }
                int nb = bi + 4;
                if (nb < NBATCH) {
#pragma unroll
                    for (int j = 0; j < 10; ++j)
                        buf[s][j] = __ldg(&g_h[(size_t)(nb * 10 + j) * NTHD + gid]);
                }
            }
        }
    }
}

// ---------------- K_C: o[t,b] = serial ascending-h FFMA over byte spikes ----------------
__global__ __launch_bounds__(256) void k_dot2(const float* __restrict__ w2) {
    __shared__ float w2s[HIDN];
    if (threadIdx.x < HIDN) w2s[threadIdx.x] = w2[threadIdx.x];
    __syncthreads();

    int t = blockIdx.x;
    int b = threadIdx.x;
    const uint4* sp = (const uint4*)(g_s1b + (size_t)t * NTHD + b * HIDN);

    float acc = 0.0f;
#pragma unroll
    for (int j = 0; j < 8; ++j) {
        uint4 v = __ldg(sp + j);
        unsigned wrd[4] = { v.x, v.y, v.z, v.w };
#pragma unroll
        for (int k = 0; k < 4; ++k) {
            unsigned w = wrd[k];
            int base = j * 16 + k * 4;
            acc = fmaf((float)(w & 0xffu),         w2s[base + 0], acc);
            acc = fmaf((float)((w >> 8) & 0xffu),  w2s[base + 1], acc);
            acc = fmaf((float)((w >> 16) & 0xffu), w2s[base + 2], acc);
            acc = fmaf((float)(w >> 24),           w2s[base + 3], acc);
        }
    }
    g_o[t * BB + b] = acc;
}

// ---------------- K_D: layer-2 scan, FULL batch, 4-deep rotating prefetch ----------------
__global__ __launch_bounds__(BB, 1) void k_scan2(float* __restrict__ out) {
    int b = threadIdx.x;

    float d, cd1, cdr;
    snn_consts(d, cd1, cdr);

    float p2 = 0.f, q2 = 0.f, pr2 = 0.f, qr2 = 0.f;
    float buf[4][10];

#pragma unroll
    for (int k = 0; k < 4; ++k)
#pragma unroll
        for (int j = 0; j < 10; ++j)
            buf[k][j] = __ldg(&g_o[(k * 10 + j) * BB + b]);

    for (int bi4 = 0; bi4 < NBATCH; bi4 += 4) {
#pragma unroll
        for (int s = 0; s < 4; ++s) {
            int bi = bi4 + s;
            if (bi < NBATCH) {
                int t0 = bi * 10;
#pragma unroll
                for (int j = 0; j < 10; ++j) {
                    alpha_step(d, cd1, p2, q2, buf[s][j]);
                    qr2 = fmaf(d, qr2, __fmul_rn(cdr, pr2));
                    float u = __fadd_rn(q2, qr2);
                    float sv = (u >= 1.0f) ? 1.0f : 0.0f;
                    pr2 = fmaf(d, pr2, sv);
                    out[b * TT + (t0 + j)] = sv;
                }
                int nb = bi + 4;
                if (nb < NBATCH) {
#pragma unroll
                    for (int j = 0; j < 10; ++j)
                        buf[s][j] = __ldg(&g_o[(nb * 10 + j) * BB + b]);
                }
            }
        }
    }
}

// ---------------- launch: 3 streams; enqueue order keeps G0 at launch #4 for ncu ----------------
extern "C" void kernel_launch(void* const* d_in, const int* in_sizes, int n_in,
                              void* d_out, int out_size) {
    const float* x = nullptr, *w1 = nullptr, *w2 = nullptr;
    for (int i = 0; i < n_in; ++i) {
        if      (in_sizes[i] == BB * TT * ENCN) x  = (const float*)d_in[i];
        else if (in_sizes[i] == HIDN * ENCN)    w1 = (const float*)d_in[i];
        else if (in_sizes[i] == HIDN)           w2 = (const float*)d_in[i];
    }

    static cudaStream_t sC = 0, sG = 0, sS = 0;
    static cudaEvent_t  evFork, evC[4], evG[4], evS;
    static int inited = 0;
    if (!inited) {
        cudaFuncSetAttribute(k_gather, cudaFuncAttributeMaxDynamicSharedMemorySize,
                             (ENCN + 1) * 64 * (int)sizeof(float));
        cudaStreamCreateWithFlags(&sC, cudaStreamNonBlocking);
        cudaStreamCreateWithFlags(&sG, cudaStreamNonBlocking);
        cudaStreamCreateWithFlags(&sS, cudaStreamNonBlocking);
        cudaEventCreateWithFlags(&evFork, cudaEventDisableTiming);
        cudaEventCreateWithFlags(&evS,    cudaEventDisableTiming);
        for (int i = 0; i < 4; ++i) {
            cudaEventCreateWithFlags(&evC[i], cudaEventDisableTiming);
            cudaEventCreateWithFlags(&evG[i], cudaEventDisableTiming);
        }
        inited = 1;
    }

    cudaEventRecord(evFork, 0);
    cudaStreamWaitEvent(sC, evFork, 0);
    cudaStreamWaitEvent(sG, evFork, 0);

    const int GSM = (ENCN + 1) * 64 * (int)sizeof(float);

    // launch #1..#4: T, C0, C1, G0  -> ncu captures G0
    k_transpose<<<(ENCN * HIDN + 255) / 256, 256, 0, sG>>>(w1);
    k_compact<<<dim3((TT + 7) / 8, CHB), 256, 0, sC>>>(x, 0 * CHB);
    cudaEventRecord(evC[0], sC);
    k_compact<<<dim3((TT + 7) / 8, CHB), 256, 0, sC>>>(x, 1 * CHB);
    cudaEventRecord(evC[1], sC);
    cudaStreamWaitEvent(sG, evC[0], 0);
    k_gather<<<dim3(CHB, 2), GTHR, GSM, sG>>>(0 * CHB);
    cudaEventRecord(evG[0], sG);

    k_compact<<<dim3((TT + 7) / 8, CHB), 256, 0, sC>>>(x, 2 * CHB);
    cudaEventRecord(evC[2], sC);
    cudaStreamWaitEvent(sG, evC[1], 0);
    k_gather<<<dim3(CHB, 2), GTHR, GSM, sG>>>(1 * CHB);
    cudaEventRecord(evG[1], sG);

    k_compact<<<dim3((TT + 7) / 8, CHB), 256, 0, sC>>>(x, 3 * CHB);
    cudaEventRecord(evC[3], sC);
    cudaStreamWaitEvent(sG, evC[2], 0);
    k_gather<<<dim3(CHB, 2), GTHR, GSM, sG>>>(2 * CHB);
    cudaEventRecord(evG[2], sG);

    cudaStreamWaitEvent(sG, evC[3], 0);
    k_gather<<<dim3(CHB, 2), GTHR, GSM, sG>>>(3 * CHB);
    cudaEventRecord(evG[3], sG);

    cudaStreamWaitEvent(sS, evG[3], 0);
    k_scan1<<<NTHD / 256, 256, 0, sS>>>();
    k_dot2<<<TT, BB, 0, sS>>>(w2);
    k_scan2<<<1, BB, 0, sS>>>((float*)d_out);
    cudaEventRecord(evS, sS);
    cudaStreamWaitEvent(0, evS, 0);
}

// round 16
// speedup vs baseline: 1.1234x; 1.0534x over previous
#include <cuda_runtime.h>
#include <math.h>

#define TT   500
#define BB   256
#define ENCN 700
#define HIDN 128
#define LCAP 128          // list capacity (u32 entries) per (b,t); mean firing 35
#define NTHD 32768        // BB*HIDN
#define CHB  64           // batch-chunk size (4 chunks pipelined)
#define NBATCH 50         // TT/10 scan batches
#define ZSENT (ENCN << 8) // sentinel byte-offset -> zero smem row (row stride 256 B)
#define GTHR 1024         // gather block threads (32 warps/SM, 1 block/SM)
#define NPRE 44           // prefetch entries (11 x uint4); P(n>44) ~ 6% -> tail loop

// ---------------- static device scratch (allocation-free rule) ----------------
__device__ float          g_w1t[ENCN * HIDN];               // w1 transposed [enc][hid]
__device__ int            g_cnt [BB * TT];                  // firing count per (b,t)
__device__ unsigned int   g_list[(size_t)BB * TT * LCAP];   // byte offsets e<<8, 4-padded
__device__ float          g_h   [(size_t)TT * BB * HIDN];   // layer-1 pre-filter activations
__device__ unsigned char  g_s1b [(size_t)TT * BB * HIDN];   // layer-1 spikes as bytes
__device__ float          g_o   [TT * BB];                  // layer-2 pre-filter input

// Constants exactly as XLA-on-GPU computes them (bit-exact — DO NOT TOUCH):
__device__ __forceinline__ void snn_consts(float& d, float& cd1, float& cdr) {
    d        = expf(-0.05f);          // libdevice __nv_expf
    float e1 = expf(1.0f);
    float c1 = __fdiv_rn(e1, 20.0f);
    cd1      = __fmul_rn(c1, d);
    float cr = __fdiv_rn(__fmul_rn(-2.0f, e1), 20.0f);
    cdr      = __fmul_rn(cr, d);
}

// ptxas-contracted scan step (bit-exact — DO NOT TOUCH):
__device__ __forceinline__ void alpha_step(float d, float cd, float& p, float& q, float in) {
    q = fmaf(d, q, __fmul_rn(cd, p));
    p = fmaf(d, p, in);
}

// ---------------- K_t: transpose w1 [hid][enc] -> [enc][hid] ----------------
__global__ void k_transpose(const float* __restrict__ w1) {
    int i = blockIdx.x * blockDim.x + threadIdx.x;
    if (i < ENCN * HIDN) {
        int e = i >> 7;
        int h = i & (HIDN - 1);
        g_w1t[i] = w1[h * ENCN + e];
    }
}

// ---------------- K0: ballot-compact u32 byte-offsets per (b,t), 4-padded ----------------
__global__ __launch_bounds__(256) void k_compact(const float* __restrict__ x, int b0) {
    int b    = b0 + blockIdx.y;
    int t    = blockIdx.x * 8 + (threadIdx.x >> 5);
    int lane = threadIdx.x & 31;
    if (t >= TT) return;

    const float4* xr4 = (const float4*)(x + (size_t)b * (TT * ENCN) + (size_t)t * ENCN);

    float4 v[6];
#pragma unroll
    for (int g = 0; g < 6; ++g) {
        int idx = g * 32 + lane;                 // float4 index, 175 per row
        v[g] = (idx < 175) ? __ldg(xr4 + idx)
                           : make_float4(0.f, 0.f, 0.f, 0.f);
    }

    unsigned int* lst = g_list + ((size_t)b * TT + t) * LCAP;
    const unsigned lt = (1u << lane) - 1u;
    int cnt = 0;
#pragma unroll
    for (int g = 0; g < 6; ++g) {
        bool f0 = v[g].x > 0.5f, f1 = v[g].y > 0.5f, f2 = v[g].z > 0.5f, f3 = v[g].w > 0.5f;
        unsigned m0 = __ballot_sync(0xffffffffu, f0);
        unsigned m1 = __ballot_sync(0xffffffffu, f1);
        unsigned m2 = __ballot_sync(0xffffffffu, f2);
        unsigned m3 = __ballot_sync(0xffffffffu, f3);
        int p = cnt + __popc(m0 & lt) + __popc(m1 & lt) + __popc(m2 & lt) + __popc(m3 & lt);
        unsigned e0s = (unsigned)((g * 128 + lane * 4) << 8);   // byte offsets, row stride 256
        if (f0) { if (p < LCAP) lst[p] = e0s;         ++p; }
        if (f1) { if (p < LCAP) lst[p] = e0s + 256;   ++p; }
        if (f2) { if (p < LCAP) lst[p] = e0s + 512;   ++p; }
        if (f3) { if (p < LCAP) lst[p] = e0s + 768;   ++p; }
        cnt += __popc(m0) + __popc(m1) + __popc(m2) + __popc(m3);
    }
    cnt = cnt < LCAP ? cnt : LCAP;
    // sentinel-pad [cnt, ceil4(cnt)) (<=3 entries) so gather groups are branch-free
    int padEnd = (cnt + 3) & ~3;
    if (padEnd > NPRE) padEnd = NPRE;            // entries beyond 44 handled by tail loop
    for (int i = cnt + lane; i < padEnd; i += 32) lst[i] = (unsigned)ZSENT;
    if (lane == 0) g_cnt[b * TT + t] = cnt;
}

// ---------------- K_A: sparse gather GEMM, 64-wide LDS.64, 32 warps/SM ----------------
// grid (CHB, 2), 1024 thr, 1 block/SM (179.5 KB smem). Warp-per-t stride 32; each lane
// covers 2 hid columns via one LDS.64 per firing enc. Crossbar-bound: max resident
// warps. Sentinel row 700 = zeros (+0.0f exact); ascending-e serial order per column.
__global__ __launch_bounds__(GTHR, 1) void k_gather(int b0) {
    extern __shared__ float w1s[];   // [701][64] = 179456 B (row 700 = zeros)
    const int b = b0 + blockIdx.x, hh = blockIdx.y;
    const int tid  = threadIdx.x;
    const int wid  = tid >> 5;       // 0..31
    const int lane = tid & 31;

    for (int i = tid; i < (ENCN + 1) * 64; i += GTHR) {
        int e = i >> 6, h = i & 63;
        w1s[i] = (e < ENCN) ? g_w1t[e * HIDN + hh * 64 + h] : 0.0f;
    }
    __syncthreads();

    const char* wbase = (const char*)w1s + lane * 8;   // per-thread column pair base

    for (int t = wid; t < TT; t += 32) {
        const int base = b * TT + t;
        const int n = __ldg(g_cnt + base);
        const uint4* l4 = (const uint4*)(g_list + (size_t)base * LCAP);

        // unconditional 11 x LDG.128 prefetch (44 entries; MLP=11)
        uint4 v[11];
#pragma unroll
        for (int r = 0; r < 11; ++r) v[r] = __ldg(l4 + r);

        const int ng = ((n < NPRE ? n : NPRE) + 3) >> 2;   // groups of 4 (= 1 uint4)
        float a0 = 0.0f, a1 = 0.0f;
#pragma unroll
        for (int g = 0; g < 11; ++g) {
            if (g < ng) {
                float2 w0 = *(const float2*)(wbase + v[g].x);
                float2 w1v = *(const float2*)(wbase + v[g].y);
                float2 w2v = *(const float2*)(wbase + v[g].z);
                float2 w3v = *(const float2*)(wbase + v[g].w);
                a0 = __fadd_rn(a0, w0.x);  a1 = __fadd_rn(a1, w0.y);
                a0 = __fadd_rn(a0, w1v.x); a1 = __fadd_rn(a1, w1v.y);
                a0 = __fadd_rn(a0, w2v.x); a1 = __fadd_rn(a1, w2v.y);
                a0 = __fadd_rn(a0, w3v.x); a1 = __fadd_rn(a1, w3v.y);
            }
        }
        // rare tail (P ~ 6%): entries 44..n-1, still ascending
        if (n > NPRE) {
            const unsigned int* lst = g_list + (size_t)base * LCAP;
            for (int k = NPRE; k < n; ++k) {
                float2 w = *(const float2*)(wbase + __ldg(lst + k));
                a0 = __fadd_rn(a0, w.x);
                a1 = __fadd_rn(a1, w.y);
            }
        }

        float2* outp = (float2*)(g_h + (size_t)t * NTHD + b * HIDN + hh * 64 + lane * 2);
        *outp = make_float2(a0, a1);
    }
}

// ---------------- K_B: layer-1 scan, FULL batch, 4-deep rotating prefetch ----------------
__global__ __launch_bounds__(256, 1) void k_scan1() {
    int gid = blockIdx.x * 256 + threadIdx.x;   // b*128 + h

    float d, cd1, cdr;
    snn_consts(d, cd1, cdr);

    float p1 = 0.f, q1 = 0.f, pr = 0.f, qr = 0.f;
    float buf[4][10];

#pragma unroll
    for (int k = 0; k < 4; ++k)
#pragma unroll
        for (int j = 0; j < 10; ++j)
            buf[k][j] = __ldg(&g_h[(size_t)(k * 10 + j) * NTHD + gid]);

    for (int bi4 = 0; bi4 < NBATCH; bi4 += 4) {
#pragma unroll
        for (int s = 0; s < 4; ++s) {
            int bi = bi4 + s;
            if (bi < NBATCH) {
                int t0 = bi * 10;
#pragma unroll
                for (int j = 0; j < 10; ++j) {
                    alpha_step(d, cd1, p1, q1, buf[s][j]);
                    qr = fmaf(d, qr, __fmul_rn(cdr, pr));
                    float u = __fadd_rn(q1, qr);
                    float sv = (u >= 1.0f) ? 1.0f : 0.0f;
                    pr = fmaf(d, pr, sv);
                    g_s1b[(size_t)(t0 + j) * NTHD + gid] = (unsigned char)(u >= 1.0f);
                }
                int nb = bi + 4;
                if (nb < NBATCH) {
#pragma unroll
                    for (int j = 0; j < 10; ++j)
                        buf[s][j] = __ldg(&g_h[(size_t)(nb * 10 + j) * NTHD + gid]);
                }
            }
        }
    }
}

// ---------------- K_C: o[t,b] = serial ascending-h FFMA over byte spikes ----------------
__global__ __launch_bounds__(256) void k_dot2(const float* __restrict__ w2) {
    __shared__ float w2s[HIDN];
    if (threadIdx.x < HIDN) w2s[threadIdx.x] = w2[threadIdx.x];
    __syncthreads();

    int t = blockIdx.x;
    int b = threadIdx.x;
    const uint4* sp = (const uint4*)(g_s1b + (size_t)t * NTHD + b * HIDN);

    float acc = 0.0f;
#pragma unroll
    for (int j = 0; j < 8; ++j) {
        uint4 v = __ldg(sp + j);
        unsigned wrd[4] = { v.x, v.y, v.z, v.w };
#pragma unroll
        for (int k = 0; k < 4; ++k) {
            unsigned w = wrd[k];
            int base = j * 16 + k * 4;
            acc = fmaf((float)(w & 0xffu),         w2s[base + 0], acc);
            acc = fmaf((float)((w >> 8) & 0xffu),  w2s[base + 1], acc);
            acc = fmaf((float)((w >> 16) & 0xffu), w2s[base + 2], acc);
            acc = fmaf((float)(w >> 24),           w2s[base + 3], acc);
        }
    }
    g_o[t * BB + b] = acc;
}

// ---------------- K_D: layer-2 scan, FULL batch, 4-deep rotating prefetch ----------------
__global__ __launch_bounds__(BB, 1) void k_scan2(float* __restrict__ out) {
    int b = threadIdx.x;

    float d, cd1, cdr;
    snn_consts(d, cd1, cdr);

    float p2 = 0.f, q2 = 0.f, pr2 = 0.f, qr2 = 0.f;
    float buf[4][10];

#pragma unroll
    for (int k = 0; k < 4; ++k)
#pragma unroll
        for (int j = 0; j < 10; ++j)
            buf[k][j] = __ldg(&g_o[(k * 10 + j) * BB + b]);

    for (int bi4 = 0; bi4 < NBATCH; bi4 += 4) {
#pragma unroll
        for (int s = 0; s < 4; ++s) {
            int bi = bi4 + s;
            if (bi < NBATCH) {
                int t0 = bi * 10;
#pragma unroll
                for (int j = 0; j < 10; ++j) {
                    alpha_step(d, cd1, p2, q2, buf[s][j]);
                    qr2 = fmaf(d, qr2, __fmul_rn(cdr, pr2));
                    float u = __fadd_rn(q2, qr2);
                    float sv = (u >= 1.0f) ? 1.0f : 0.0f;
                    pr2 = fmaf(d, pr2, sv);
                    out[b * TT + (t0 + j)] = sv;
                }
                int nb = bi + 4;
                if (nb < NBATCH) {
#pragma unroll
                    for (int j = 0; j < 10; ++j)
                        buf[s][j] = __ldg(&g_o[(nb * 10 + j) * BB + b]);
                }
            }
        }
    }
}

// ---------------- launch: 3 streams; enqueue order keeps G0 at launch #4 for ncu ----------------
extern "C" void kernel_launch(void* const* d_in, const int* in_sizes, int n_in,
                              void* d_out, int out_size) {
    const float* x = nullptr, *w1 = nullptr, *w2 = nullptr;
    for (int i = 0; i < n_in; ++i) {
        if      (in_sizes[i] == BB * TT * ENCN) x  = (const float*)d_in[i];
        else if (in_sizes[i] == HIDN * ENCN)    w1 = (const float*)d_in[i];
        else if (in_sizes[i] == HIDN)           w2 = (const float*)d_in[i];
    }

    static cudaStream_t sC = 0, sG = 0, sS = 0;
    static cudaEvent_t  evFork, evC[4], evG[4], evS;
    static int inited = 0;
    if (!inited) {
        cudaFuncSetAttribute(k_gather, cudaFuncAttributeMaxDynamicSharedMemorySize,
                             (ENCN + 1) * 64 * (int)sizeof(float));
        cudaStreamCreateWithFlags(&sC, cudaStreamNonBlocking);
        cudaStreamCreateWithFlags(&sG, cudaStreamNonBlocking);
        cudaStreamCreateWithFlags(&sS, cudaStreamNonBlocking);
        cudaEventCreateWithFlags(&evFork, cudaEventDisableTiming);
        cudaEventCreateWithFlags(&evS,    cudaEventDisableTiming);
        for (int i = 0; i < 4; ++i) {
            cudaEventCreateWithFlags(&evC[i], cudaEventDisableTiming);
            cudaEventCreateWithFlags(&evG[i], cudaEventDisableTiming);
        }
        inited = 1;
    }

    cudaEventRecord(evFork, 0);
    cudaStreamWaitEvent(sC, evFork, 0);
    cudaStreamWaitEvent(sG, evFork, 0);

    const int GSM = (ENCN + 1) * 64 * (int)sizeof(float);

    // launch #1..#4: T, C0, C1, G0  -> ncu captures G0
    k_transpose<<<(ENCN * HIDN + 255) / 256, 256, 0, sG>>>(w1);
    k_compact<<<dim3((TT + 7) / 8, CHB), 256, 0, sC>>>(x, 0 * CHB);
    cudaEventRecord(evC[0], sC);
    k_compact<<<dim3((TT + 7) / 8, CHB), 256, 0, sC>>>(x, 1 * CHB);
    cudaEventRecord(evC[1], sC);
    cudaStreamWaitEvent(sG, evC[0], 0);
    k_gather<<<dim3(CHB, 2), GTHR, GSM, sG>>>(0 * CHB);
    cudaEventRecord(evG[0], sG);

    k_compact<<<dim3((TT + 7) / 8, CHB), 256, 0, sC>>>(x, 2 * CHB);
    cudaEventRecord(evC[2], sC);
    cudaStreamWaitEvent(sG, evC[1], 0);
    k_gather<<<dim3(CHB, 2), GTHR, GSM, sG>>>(1 * CHB);
    cudaEventRecord(evG[1], sG);

    k_compact<<<dim3((TT + 7) / 8, CHB), 256, 0, sC>>>(x, 3 * CHB);
    cudaEventRecord(evC[3], sC);
    cudaStreamWaitEvent(sG, evC[2], 0);
    k_gather<<<dim3(CHB, 2), GTHR, GSM, sG>>>(2 * CHB);
    cudaEventRecord(evG[2], sG);

    cudaStreamWaitEvent(sG, evC[3], 0);
    k_gather<<<dim3(CHB, 2), GTHR, GSM, sG>>>(3 * CHB);
    cudaEventRecord(evG[3], sG);

    cudaStreamWaitEvent(sS, evG[3], 0);
    k_scan1<<<NTHD / 256, 256, 0, sS>>>();
    k_dot2<<<TT, BB, 0, sS>>>(w2);
    k_scan2<<<1, BB, 0, sS>>>((float*)d_out);
    cudaEventRecord(evS, sS);
    cudaStreamWaitEvent(0, evS, 0);
}